// round 1
// baseline (speedup 1.0000x reference)
#include <cuda_runtime.h>
#include <cuda_bf16.h>
#include <mma.h>

using namespace nvcuda;
typedef __nv_bfloat16 bf16;

// Problem constants
#define BB   2
#define SS   2048
#define DD   1024
#define HH   8
#define DHH  128
#define MTOT (BB*SS)          // 4096 rows
#define HEADLEN (SS*DHH)      // 262144 elems per (b,h) slice

// GEMM tiling
#define BM 128
#define BN 128
#define BK 32
#define KPAD 40               // bf16 pitch (80B, 16B aligned)
#define CPITCH 132            // fp32 pitch (528B, 16B aligned)
#define GEMM_SMEM (BM*CPITCH*4)   // 67584 B (C tile reuses A/B region)

// Flash tiling
#define BR 64
#define BC 128
#define QPITCH 136            // bf16 pitch
#define SPITCH 132            // fp32 pitch
#define OFF_QS   0
#define OFF_KVS  (BR*QPITCH*2)                 // 17408
#define OFF_PS   (OFF_KVS + BC*QPITCH*2)       // 52224
#define OFF_SS   (OFF_PS + BR*QPITCH*2)        // 69632
#define OFF_OS   (OFF_SS + BR*SPITCH*4)        // 103424
#define FLASH_SMEM (OFF_OS + BR*SPITCH*4)      // 137216

// Scratch (static device globals; allocation at load time, not in kernel_launch)
__device__ bf16 g_x [MTOT*DD];
__device__ bf16 g_qs[MTOT*DD];
__device__ bf16 g_ks[MTOT*DD];
__device__ bf16 g_vs[MTOT*DD];
__device__ bf16 g_ao[MTOT*DD];
__device__ bf16 g_w [4*DD*DD];   // Wq,Wk,Wv,Wo in bf16

// ---------------------------------------------------------------------------
// Weight fp32 -> bf16 convert
// ---------------------------------------------------------------------------
__global__ void cvt_w_kernel(const float* __restrict__ wq, const float* __restrict__ wk,
                             const float* __restrict__ wv, const float* __restrict__ wo)
{
    int idx = blockIdx.x * blockDim.x + threadIdx.x;   // exactly 4*2^20 threads
    int which = idx >> 20;
    int off   = idx & ((1 << 20) - 1);
    const float* src = (which == 0) ? wq : (which == 1) ? wk : (which == 2) ? wv : wo;
    g_w[idx] = __float2bfloat16(src[off]);
}

// ---------------------------------------------------------------------------
// LayerNorm: one block (256 threads) per row of 1024
// ---------------------------------------------------------------------------
__global__ void ln_kernel(const float* __restrict__ q,
                          const float* __restrict__ gamma,
                          const float* __restrict__ beta)
{
    int row = blockIdx.x;
    int t = threadIdx.x;
    const float4 v = ((const float4*)(q + (size_t)row * DD))[t];
    float s  = v.x + v.y + v.z + v.w;
    float sq = v.x*v.x + v.y*v.y + v.z*v.z + v.w*v.w;
    #pragma unroll
    for (int o = 16; o > 0; o >>= 1) {
        s  += __shfl_xor_sync(0xffffffffu, s,  o);
        sq += __shfl_xor_sync(0xffffffffu, sq, o);
    }
    __shared__ float ss[8], ssq[8];
    if ((t & 31) == 0) { ss[t >> 5] = s; ssq[t >> 5] = sq; }
    __syncthreads();
    if (t == 0) {
        float a = 0.f, bsum = 0.f;
        #pragma unroll
        for (int i = 0; i < 8; i++) { a += ss[i]; bsum += ssq[i]; }
        ss[0] = a; ssq[0] = bsum;
    }
    __syncthreads();
    const float mean = ss[0] * (1.0f / DD);
    const float var  = ssq[0] * (1.0f / DD) - mean * mean;
    const float rstd = rsqrtf(var + 1e-5f);
    const float4 g  = ((const float4*)gamma)[t];
    const float4 be = ((const float4*)beta)[t];
    bf16* out = g_x + (size_t)row * DD + t * 4;
    out[0] = __float2bfloat16((v.x - mean) * rstd * g.x + be.x);
    out[1] = __float2bfloat16((v.y - mean) * rstd * g.y + be.y);
    out[2] = __float2bfloat16((v.z - mean) * rstd * g.z + be.z);
    out[3] = __float2bfloat16((v.w - mean) * rstd * g.w + be.w);
}

// ---------------------------------------------------------------------------
// bf16 WMMA GEMM: C[m,n] = sum_k A[m,k] * W[n,k] + bias[n]  (+residual, fp32 out)
// 256 threads = 8 warps in 4x2 grid; warp tile 32x64 = 2x4 frags of 16x16
// ---------------------------------------------------------------------------
__device__ __forceinline__ void gemm_body(const bf16* __restrict__ A,
                                          const bf16* __restrict__ W,
                                          const float* __restrict__ bias,
                                          bf16* __restrict__ outB,
                                          float* __restrict__ outF,
                                          const float* __restrict__ resid)
{
    extern __shared__ char smem[];
    bf16*  As = (bf16*)smem;                     // [BM][KPAD]
    bf16*  Bs = (bf16*)(smem + BM * KPAD * 2);   // [BN][KPAD]
    float* Cs = (float*)smem;                    // [BM][CPITCH] (reused after loop)

    const int tid = threadIdx.x;
    const int wid = tid >> 5;
    const int wr  = wid >> 1;   // 0..3 -> 32-row block
    const int wc  = wid & 1;    // 0..1 -> 64-col block
    const int m0  = blockIdx.y * BM;
    const int n0  = blockIdx.x * BN;

    wmma::fragment<wmma::accumulator, 16, 16, 16, float> acc[2][4];
    #pragma unroll
    for (int i = 0; i < 2; i++)
        #pragma unroll
        for (int j = 0; j < 4; j++) wmma::fill_fragment(acc[i][j], 0.0f);

    for (int k0 = 0; k0 < DD; k0 += BK) {
        #pragma unroll
        for (int l = 0; l < 2; l++) {
            int idx = tid + l * 256;             // 0..511
            int r  = idx >> 2;                   // 0..127
            int ks = (idx & 3) * 8;              // 0,8,16,24
            *(uint4*)(As + r * KPAD + ks) = *(const uint4*)(A + (size_t)(m0 + r) * DD + k0 + ks);
            *(uint4*)(Bs + r * KPAD + ks) = *(const uint4*)(W + (size_t)(n0 + r) * DD + k0 + ks);
        }
        __syncthreads();
        #pragma unroll
        for (int kk = 0; kk < BK; kk += 16) {
            wmma::fragment<wmma::matrix_a, 16, 16, 16, bf16, wmma::row_major> af[2];
            wmma::fragment<wmma::matrix_b, 16, 16, 16, bf16, wmma::col_major> wf[4];
            #pragma unroll
            for (int i = 0; i < 2; i++)
                wmma::load_matrix_sync(af[i], As + (wr * 32 + i * 16) * KPAD + kk, KPAD);
            #pragma unroll
            for (int j = 0; j < 4; j++)
                wmma::load_matrix_sync(wf[j], Bs + (wc * 64 + j * 16) * KPAD + kk, KPAD);
            #pragma unroll
            for (int i = 0; i < 2; i++)
                #pragma unroll
                for (int j = 0; j < 4; j++)
                    wmma::mma_sync(acc[i][j], af[i], wf[j], acc[i][j]);
        }
        __syncthreads();
    }

    #pragma unroll
    for (int i = 0; i < 2; i++)
        #pragma unroll
        for (int j = 0; j < 4; j++)
            wmma::store_matrix_sync(Cs + (wr * 32 + i * 16) * CPITCH + wc * 64 + j * 16,
                                    acc[i][j], CPITCH, wmma::mem_row_major);
    __syncthreads();

    for (int i = tid; i < BM * BN; i += 256) {
        int r = i >> 7, c = i & 127;
        float v = Cs[r * CPITCH + c] + bias[n0 + c];
        size_t gi = (size_t)(m0 + r) * DD + n0 + c;
        if (outF) outF[gi] = v + resid[gi];
        else      outB[gi] = __float2bfloat16(v);
    }
}

__global__ __launch_bounds__(256) void gemm_qkv_kernel(const float* __restrict__ bq,
                                                       const float* __restrict__ bk,
                                                       const float* __restrict__ bv)
{
    int z = blockIdx.z;
    const bf16* W    = g_w + (size_t)z * DD * DD;
    const float* bias = (z == 0) ? bq : (z == 1) ? bk : bv;
    bf16* out        = (z == 0) ? g_qs : (z == 1) ? g_ks : g_vs;
    gemm_body(g_x, W, bias, out, nullptr, nullptr);
}

__global__ __launch_bounds__(256) void gemm_out_kernel(const float* __restrict__ bo,
                                                       const float* __restrict__ resid,
                                                       float* __restrict__ out)
{
    gemm_body(g_ao, g_w + (size_t)3 * DD * DD, bo, nullptr, out, resid);
}

// ---------------------------------------------------------------------------
// Flash attention per (b,h, 64-row query block). Heads are contiguous slices.
// 256 threads = 8 warps in 2x4 grid; warp tile 32x32 = 2x2 frags
// ---------------------------------------------------------------------------
__global__ __launch_bounds__(256) void flash_kernel()
{
    extern __shared__ char smem[];
    bf16*  Qs  = (bf16*)(smem + OFF_QS);    // [BR][QPITCH]
    bf16*  KVs = (bf16*)(smem + OFF_KVS);   // [BC][QPITCH] (K then V, reused)
    bf16*  Ps  = (bf16*)(smem + OFF_PS);    // [BR][QPITCH]
    float* Ss  = (float*)(smem + OFF_SS);   // [BR][SPITCH]
    float* Os  = (float*)(smem + OFF_OS);   // [BR][SPITCH]

    const int tid = threadIdx.x;
    const int wid = tid >> 5;
    const int wr  = wid >> 2;    // 0..1
    const int wc  = wid & 3;     // 0..3
    const int qb  = blockIdx.x;  // 0..31
    const int h   = blockIdx.y;  // 0..7
    const int b   = blockIdx.z;  // 0..1
    const size_t headoff = (size_t)b * SS * DD + (size_t)h * HEADLEN;

    // Load Q tile [64][128]
    #pragma unroll
    for (int i = 0; i < 4; i++) {
        int li = tid + i * 256;
        int r = li >> 4, d0 = (li & 15) * 8;
        *(uint4*)(Qs + r * QPITCH + d0) =
            *(const uint4*)(g_qs + headoff + (size_t)(qb * BR + r) * DHH + d0);
    }
    for (int i = tid; i < BR * SPITCH; i += 256) Os[i] = 0.0f;

    const int row = tid >> 2;          // 0..63 (4 threads per row)
    const int c0  = (tid & 3) * 32;
    float m_run = -1e30f;
    float l_run = 0.0f;
    __syncthreads();

    for (int t = 0; t < SS / BC; t++) {
        // Load K tile
        #pragma unroll
        for (int i = 0; i < 8; i++) {
            int li = tid + i * 256;
            int r = li >> 4, d0 = (li & 15) * 8;
            *(uint4*)(KVs + r * QPITCH + d0) =
                *(const uint4*)(g_ks + headoff + (size_t)(t * BC + r) * DHH + d0);
        }
        __syncthreads();

        // S = Q K^T  (64x128, K-dim = 128)
        {
            wmma::fragment<wmma::accumulator, 16, 16, 16, float> sacc[2][2];
            #pragma unroll
            for (int i = 0; i < 2; i++)
                #pragma unroll
                for (int j = 0; j < 2; j++) wmma::fill_fragment(sacc[i][j], 0.0f);
            #pragma unroll
            for (int kk = 0; kk < DHH; kk += 16) {
                wmma::fragment<wmma::matrix_a, 16, 16, 16, bf16, wmma::row_major> af[2];
                wmma::fragment<wmma::matrix_b, 16, 16, 16, bf16, wmma::col_major> kf[2];
                #pragma unroll
                for (int i = 0; i < 2; i++)
                    wmma::load_matrix_sync(af[i], Qs + (wr * 32 + i * 16) * QPITCH + kk, QPITCH);
                #pragma unroll
                for (int j = 0; j < 2; j++)
                    wmma::load_matrix_sync(kf[j], KVs + (wc * 32 + j * 16) * QPITCH + kk, QPITCH);
                #pragma unroll
                for (int i = 0; i < 2; i++)
                    #pragma unroll
                    for (int j = 0; j < 2; j++)
                        wmma::mma_sync(sacc[i][j], af[i], kf[j], sacc[i][j]);
            }
            #pragma unroll
            for (int i = 0; i < 2; i++)
                #pragma unroll
                for (int j = 0; j < 2; j++)
                    wmma::store_matrix_sync(Ss + (wr * 32 + i * 16) * SPITCH + wc * 32 + j * 16,
                                            sacc[i][j], SPITCH, wmma::mem_row_major);
        }
        __syncthreads();

        // Load V tile over K tile (S already materialized), then online softmax
        #pragma unroll
        for (int i = 0; i < 8; i++) {
            int li = tid + i * 256;
            int r = li >> 4, d0 = (li & 15) * 8;
            *(uint4*)(KVs + r * QPITCH + d0) =
                *(const uint4*)(g_vs + headoff + (size_t)(t * BC + r) * DHH + d0);
        }
        {
            float* srow = Ss + row * SPITCH + c0;
            float tmax = -1e30f;
            #pragma unroll
            for (int c = 0; c < 32; c++) tmax = fmaxf(tmax, srow[c]);
            tmax = fmaxf(tmax, __shfl_xor_sync(0xffffffffu, tmax, 1));
            tmax = fmaxf(tmax, __shfl_xor_sync(0xffffffffu, tmax, 2));
            float m_new = fmaxf(m_run, tmax);
            float alpha = __expf(m_run - m_new);
            float psum = 0.0f;
            bf16* prow = Ps + row * QPITCH + c0;
            #pragma unroll
            for (int c = 0; c < 32; c++) {
                float p = __expf(srow[c] - m_new);
                prow[c] = __float2bfloat16(p);
                psum += p;
            }
            psum += __shfl_xor_sync(0xffffffffu, psum, 1);
            psum += __shfl_xor_sync(0xffffffffu, psum, 2);
            l_run = l_run * alpha + psum;
            m_run = m_new;
            float* orow = Os + row * SPITCH + c0;
            #pragma unroll
            for (int c = 0; c < 32; c++) orow[c] *= alpha;
        }
        __syncthreads();

        // O += P V  (64x128, K-dim = 128)
        {
            wmma::fragment<wmma::accumulator, 16, 16, 16, float> oacc[2][2];
            #pragma unroll
            for (int i = 0; i < 2; i++)
                #pragma unroll
                for (int j = 0; j < 2; j++)
                    wmma::load_matrix_sync(oacc[i][j],
                        Os + (wr * 32 + i * 16) * SPITCH + wc * 32 + j * 16,
                        SPITCH, wmma::mem_row_major);
            #pragma unroll
            for (int kk = 0; kk < BC; kk += 16) {
                wmma::fragment<wmma::matrix_a, 16, 16, 16, bf16, wmma::row_major> pf[2];
                wmma::fragment<wmma::matrix_b, 16, 16, 16, bf16, wmma::row_major> vf[2];
                #pragma unroll
                for (int i = 0; i < 2; i++)
                    wmma::load_matrix_sync(pf[i], Ps + (wr * 32 + i * 16) * QPITCH + kk, QPITCH);
                #pragma unroll
                for (int j = 0; j < 2; j++)
                    wmma::load_matrix_sync(vf[j], KVs + kk * QPITCH + wc * 32 + j * 16, QPITCH);
                #pragma unroll
                for (int i = 0; i < 2; i++)
                    #pragma unroll
                    for (int j = 0; j < 2; j++)
                        wmma::mma_sync(oacc[i][j], pf[i], vf[j], oacc[i][j]);
            }
            #pragma unroll
            for (int i = 0; i < 2; i++)
                #pragma unroll
                for (int j = 0; j < 2; j++)
                    wmma::store_matrix_sync(Os + (wr * 32 + i * 16) * SPITCH + wc * 32 + j * 16,
                                            oacc[i][j], SPITCH, wmma::mem_row_major);
        }
        __syncthreads();
    }

    // Epilogue: out = O / l / sqrt(D), write bf16 to g_ao at the head slice
    {
        float scale = 1.0f / (l_run * 32.0f);   // sqrt(1024) = 32
        float* orow = Os + row * SPITCH + c0;
        bf16* dst = g_ao + headoff + (size_t)(qb * BR + row) * DHH + c0;
        #pragma unroll
        for (int c = 0; c < 32; c++)
            dst[c] = __float2bfloat16(orow[c] * scale);
    }
}

// ---------------------------------------------------------------------------
extern "C" void kernel_launch(void* const* d_in, const int* in_sizes, int n_in,
                              void* d_out, int out_size)
{
    const float* q     = (const float*)d_in[0];
    const float* Wq    = (const float*)d_in[1];
    const float* bq    = (const float*)d_in[2];
    const float* Wk    = (const float*)d_in[3];
    const float* bk    = (const float*)d_in[4];
    const float* Wv    = (const float*)d_in[5];
    const float* bv    = (const float*)d_in[6];
    const float* Wo    = (const float*)d_in[7];
    const float* bo    = (const float*)d_in[8];
    const float* gamma = (const float*)d_in[9];
    const float* beta  = (const float*)d_in[10];
    float* out = (float*)d_out;

    cudaFuncSetAttribute(gemm_qkv_kernel, cudaFuncAttributeMaxDynamicSharedMemorySize, GEMM_SMEM);
    cudaFuncSetAttribute(gemm_out_kernel, cudaFuncAttributeMaxDynamicSharedMemorySize, GEMM_SMEM);
    cudaFuncSetAttribute(flash_kernel,    cudaFuncAttributeMaxDynamicSharedMemorySize, FLASH_SMEM);

    cvt_w_kernel<<<4096, 1024>>>(Wq, Wk, Wv, Wo);
    ln_kernel<<<MTOT, 256>>>(q, gamma, beta);
    gemm_qkv_kernel<<<dim3(DD / BN, MTOT / BM, 3), 256, GEMM_SMEM>>>(bq, bk, bv);
    flash_kernel<<<dim3(SS / BR, HH, BB), 256, FLASH_SMEM>>>();
    gemm_out_kernel<<<dim3(DD / BN, MTOT / BM, 1), 256, GEMM_SMEM>>>(bo, q, out);
}

// round 2
// speedup vs baseline: 1.7465x; 1.7465x over previous
#include <cuda_runtime.h>
#include <cuda_bf16.h>
#include <mma.h>

using namespace nvcuda;
typedef __nv_bfloat16 bf16;

// Problem constants
#define BB   2
#define SS   2048
#define DD   1024
#define HH   8
#define DHH  128
#define MTOT (BB*SS)          // 4096 rows
#define HEADLEN (SS*DHH)      // 262144 elems per (b,h) slice

// GEMM tiling
#define BM 128
#define BN 128
#define BK 32
#define KPAD 40               // bf16 pitch (80B, 16B aligned)
#define CPITCH 132            // fp32 pitch (528B, 16B aligned)
#define GEMM_SMEM (BM*CPITCH*4)   // 67584 B (C tile reuses A/B region)

// Flash v2 tiling (register-resident FA2)
#define F_BR 64               // rows per block (4 warps x 16)
#define F_BC 64               // kv cols per iteration
#define F_PITCH 136           // bf16 smem pitch (272B)
#define F_TILE (F_BC*F_PITCH) // elems per tile buffer
#define FLASH2_SMEM (4*F_TILE*2)   // K0,K1,V0,V1 = 69632 B

// Scratch (static device globals)
__device__ bf16 g_x [MTOT*DD];
__device__ bf16 g_qs[MTOT*DD];
__device__ bf16 g_ks[MTOT*DD];
__device__ bf16 g_vs[MTOT*DD];
__device__ bf16 g_ao[MTOT*DD];
__device__ bf16 g_w [4*DD*DD];   // Wq,Wk,Wv,Wo in bf16

// ---------------------------------------------------------------------------
// cp.async helpers
// ---------------------------------------------------------------------------
__device__ __forceinline__ void cpasync16(void* sdst, const void* gsrc)
{
    unsigned sa = (unsigned)__cvta_generic_to_shared(sdst);
    asm volatile("cp.async.cg.shared.global [%0], [%1], 16;\n" :: "r"(sa), "l"(gsrc));
}
#define CP_COMMIT() asm volatile("cp.async.commit_group;\n")
#define CP_WAIT(n)  asm volatile("cp.async.wait_group %0;\n" :: "n"(n))

// ---------------------------------------------------------------------------
// Weight fp32 -> bf16 convert
// ---------------------------------------------------------------------------
__global__ void cvt_w_kernel(const float* __restrict__ wq, const float* __restrict__ wk,
                             const float* __restrict__ wv, const float* __restrict__ wo)
{
    int idx = blockIdx.x * blockDim.x + threadIdx.x;
    int which = idx >> 20;
    int off   = idx & ((1 << 20) - 1);
    const float* src = (which == 0) ? wq : (which == 1) ? wk : (which == 2) ? wv : wo;
    g_w[idx] = __float2bfloat16(src[off]);
}

// ---------------------------------------------------------------------------
// LayerNorm: one block (256 threads) per row of 1024
// ---------------------------------------------------------------------------
__global__ void ln_kernel(const float* __restrict__ q,
                          const float* __restrict__ gamma,
                          const float* __restrict__ beta)
{
    int row = blockIdx.x;
    int t = threadIdx.x;
    const float4 v = ((const float4*)(q + (size_t)row * DD))[t];
    float s  = v.x + v.y + v.z + v.w;
    float sq = v.x*v.x + v.y*v.y + v.z*v.z + v.w*v.w;
    #pragma unroll
    for (int o = 16; o > 0; o >>= 1) {
        s  += __shfl_xor_sync(0xffffffffu, s,  o);
        sq += __shfl_xor_sync(0xffffffffu, sq, o);
    }
    __shared__ float ss[8], ssq[8];
    if ((t & 31) == 0) { ss[t >> 5] = s; ssq[t >> 5] = sq; }
    __syncthreads();
    if (t == 0) {
        float a = 0.f, bsum = 0.f;
        #pragma unroll
        for (int i = 0; i < 8; i++) { a += ss[i]; bsum += ssq[i]; }
        ss[0] = a; ssq[0] = bsum;
    }
    __syncthreads();
    const float mean = ss[0] * (1.0f / DD);
    const float var  = ssq[0] * (1.0f / DD) - mean * mean;
    const float rstd = rsqrtf(var + 1e-5f);
    const float4 g  = ((const float4*)gamma)[t];
    const float4 be = ((const float4*)beta)[t];
    bf16* out = g_x + (size_t)row * DD + t * 4;
    out[0] = __float2bfloat16((v.x - mean) * rstd * g.x + be.x);
    out[1] = __float2bfloat16((v.y - mean) * rstd * g.y + be.y);
    out[2] = __float2bfloat16((v.z - mean) * rstd * g.z + be.z);
    out[3] = __float2bfloat16((v.w - mean) * rstd * g.w + be.w);
}

// ---------------------------------------------------------------------------
// bf16 WMMA GEMM (unchanged from R0): C = A @ W^T + bias (+residual)
// ---------------------------------------------------------------------------
__device__ __forceinline__ void gemm_body(const bf16* __restrict__ A,
                                          const bf16* __restrict__ W,
                                          const float* __restrict__ bias,
                                          bf16* __restrict__ outB,
                                          float* __restrict__ outF,
                                          const float* __restrict__ resid)
{
    extern __shared__ char smem[];
    bf16*  As = (bf16*)smem;
    bf16*  Bs = (bf16*)(smem + BM * KPAD * 2);
    float* Cs = (float*)smem;

    const int tid = threadIdx.x;
    const int wid = tid >> 5;
    const int wr  = wid >> 1;
    const int wc  = wid & 1;
    const int m0  = blockIdx.y * BM;
    const int n0  = blockIdx.x * BN;

    wmma::fragment<wmma::accumulator, 16, 16, 16, float> acc[2][4];
    #pragma unroll
    for (int i = 0; i < 2; i++)
        #pragma unroll
        for (int j = 0; j < 4; j++) wmma::fill_fragment(acc[i][j], 0.0f);

    for (int k0 = 0; k0 < DD; k0 += BK) {
        #pragma unroll
        for (int l = 0; l < 2; l++) {
            int idx = tid + l * 256;
            int r  = idx >> 2;
            int ks = (idx & 3) * 8;
            *(uint4*)(As + r * KPAD + ks) = *(const uint4*)(A + (size_t)(m0 + r) * DD + k0 + ks);
            *(uint4*)(Bs + r * KPAD + ks) = *(const uint4*)(W + (size_t)(n0 + r) * DD + k0 + ks);
        }
        __syncthreads();
        #pragma unroll
        for (int kk = 0; kk < BK; kk += 16) {
            wmma::fragment<wmma::matrix_a, 16, 16, 16, bf16, wmma::row_major> af[2];
            wmma::fragment<wmma::matrix_b, 16, 16, 16, bf16, wmma::col_major> wf[4];
            #pragma unroll
            for (int i = 0; i < 2; i++)
                wmma::load_matrix_sync(af[i], As + (wr * 32 + i * 16) * KPAD + kk, KPAD);
            #pragma unroll
            for (int j = 0; j < 4; j++)
                wmma::load_matrix_sync(wf[j], Bs + (wc * 64 + j * 16) * KPAD + kk, KPAD);
            #pragma unroll
            for (int i = 0; i < 2; i++)
                #pragma unroll
                for (int j = 0; j < 4; j++)
                    wmma::mma_sync(acc[i][j], af[i], wf[j], acc[i][j]);
        }
        __syncthreads();
    }

    #pragma unroll
    for (int i = 0; i < 2; i++)
        #pragma unroll
        for (int j = 0; j < 4; j++)
            wmma::store_matrix_sync(Cs + (wr * 32 + i * 16) * CPITCH + wc * 64 + j * 16,
                                    acc[i][j], CPITCH, wmma::mem_row_major);
    __syncthreads();

    for (int i = tid; i < BM * BN; i += 256) {
        int r = i >> 7, c = i & 127;
        float v = Cs[r * CPITCH + c] + bias[n0 + c];
        size_t gi = (size_t)(m0 + r) * DD + n0 + c;
        if (outF) outF[gi] = v + resid[gi];
        else      outB[gi] = __float2bfloat16(v);
    }
}

__global__ __launch_bounds__(256) void gemm_qkv_kernel(const float* __restrict__ bq,
                                                       const float* __restrict__ bk,
                                                       const float* __restrict__ bv)
{
    int z = blockIdx.z;
    const bf16* W     = g_w + (size_t)z * DD * DD;
    const float* bias = (z == 0) ? bq : (z == 1) ? bk : bv;
    bf16* out         = (z == 0) ? g_qs : (z == 1) ? g_ks : g_vs;
    gemm_body(g_x, W, bias, out, nullptr, nullptr);
}

__global__ __launch_bounds__(256) void gemm_out_kernel(const float* __restrict__ bo,
                                                       const float* __restrict__ resid,
                                                       float* __restrict__ out)
{
    gemm_body(g_ao, g_w + (size_t)3 * DD * DD, bo, nullptr, out, resid);
}

// ---------------------------------------------------------------------------
// Flash v2: register-resident FA2 with mma.sync.m16n8k16 + cp.async pipeline
// 128 threads = 4 warps; each warp owns 16 query rows (BR=64/block)
// ---------------------------------------------------------------------------
__device__ __forceinline__ void mma16816(float* c, const unsigned* a, unsigned b0, unsigned b1)
{
    asm volatile(
        "mma.sync.aligned.m16n8k16.row.col.f32.bf16.bf16.f32 "
        "{%0,%1,%2,%3}, {%4,%5,%6,%7}, {%8,%9}, {%0,%1,%2,%3};"
        : "+f"(c[0]), "+f"(c[1]), "+f"(c[2]), "+f"(c[3])
        : "r"(a[0]), "r"(a[1]), "r"(a[2]), "r"(a[3]), "r"(b0), "r"(b1));
}

__device__ __forceinline__ unsigned packbf2(float x, float y)
{
    __nv_bfloat162 p = __float22bfloat162_rn(make_float2(x, y));
    return *(unsigned*)&p;
}

__global__ __launch_bounds__(128) void flash2_kernel()
{
    extern __shared__ bf16 fs[];
    bf16* Kbuf[2] = { fs,              fs + F_TILE };
    bf16* Vbuf[2] = { fs + 2*F_TILE,   fs + 3*F_TILE };

    const int tid  = threadIdx.x;
    const int wid  = tid >> 5;
    const int lane = tid & 31;
    const int quad = lane >> 2;    // groupID 0..7
    const int qt   = lane & 3;     // threadID in group
    const int qb   = blockIdx.x;   // 0..31
    const int h    = blockIdx.y;
    const int b    = blockIdx.z;
    const size_t headoff = (size_t)b * SS * DD + (size_t)h * HEADLEN;
    const bf16* Kg = g_ks + headoff;
    const bf16* Vg = g_vs + headoff;

    // Load this warp's Q rows into A-fragments (16 rows x 128 k)
    const int grow1 = qb * F_BR + wid * 16 + quad;
    const int grow2 = grow1 + 8;
    const bf16* Qg = g_qs + headoff;
    unsigned aq[8][4];
    #pragma unroll
    for (int kt = 0; kt < 8; kt++) {
        aq[kt][0] = *(const unsigned*)(Qg + (size_t)grow1 * DHH + kt * 16 + 2 * qt);
        aq[kt][1] = *(const unsigned*)(Qg + (size_t)grow2 * DHH + kt * 16 + 2 * qt);
        aq[kt][2] = *(const unsigned*)(Qg + (size_t)grow1 * DHH + kt * 16 + 2 * qt + 8);
        aq[kt][3] = *(const unsigned*)(Qg + (size_t)grow2 * DHH + kt * 16 + 2 * qt + 8);
    }

    float oacc[16][4];
    #pragma unroll
    for (int nt = 0; nt < 16; nt++)
        #pragma unroll
        for (int i = 0; i < 4; i++) oacc[nt][i] = 0.0f;
    float m1 = -1e30f, m2 = -1e30f, l1 = 0.0f, l2 = 0.0f;

    // prefetch tile 0
    {
        #pragma unroll
        for (int i = 0; i < 8; i++) {
            int idx = tid + i * 128;
            int r = idx >> 4, c = (idx & 15) * 8;
            cpasync16(Kbuf[0] + r * F_PITCH + c, Kg + (size_t)r * DHH + c);
            cpasync16(Vbuf[0] + r * F_PITCH + c, Vg + (size_t)r * DHH + c);
        }
        CP_COMMIT();
    }

    const int NT = SS / F_BC;   // 32
    for (int t = 0; t < NT; t++) {
        int cur = t & 1;
        if (t + 1 < NT) {
            int nxt = cur ^ 1;
            #pragma unroll
            for (int i = 0; i < 8; i++) {
                int idx = tid + i * 128;
                int r = idx >> 4, c = (idx & 15) * 8;
                cpasync16(Kbuf[nxt] + r * F_PITCH + c, Kg + (size_t)((t + 1) * F_BC + r) * DHH + c);
                cpasync16(Vbuf[nxt] + r * F_PITCH + c, Vg + (size_t)((t + 1) * F_BC + r) * DHH + c);
            }
            CP_COMMIT();
            CP_WAIT(1);
        } else {
            CP_WAIT(0);
        }
        __syncthreads();

        // ---- S = Q K^T : sacc[8 ntiles][4] ----
        float sacc[8][4];
        #pragma unroll
        for (int nt = 0; nt < 8; nt++)
            #pragma unroll
            for (int i = 0; i < 4; i++) sacc[nt][i] = 0.0f;

        const bf16* Ks = Kbuf[cur];
        #pragma unroll
        for (int kt = 0; kt < 8; kt++) {
            #pragma unroll
            for (int nt = 0; nt < 8; nt++) {
                unsigned b0 = *(const unsigned*)(Ks + (nt * 8 + quad) * F_PITCH + kt * 16 + 2 * qt);
                unsigned b1 = *(const unsigned*)(Ks + (nt * 8 + quad) * F_PITCH + kt * 16 + 2 * qt + 8);
                mma16816(sacc[nt], aq[kt], b0, b1);
            }
        }

        // ---- online softmax in registers ----
        float rmax1 = -1e30f, rmax2 = -1e30f;
        #pragma unroll
        for (int nt = 0; nt < 8; nt++) {
            rmax1 = fmaxf(rmax1, fmaxf(sacc[nt][0], sacc[nt][1]));
            rmax2 = fmaxf(rmax2, fmaxf(sacc[nt][2], sacc[nt][3]));
        }
        rmax1 = fmaxf(rmax1, __shfl_xor_sync(0xffffffffu, rmax1, 1));
        rmax1 = fmaxf(rmax1, __shfl_xor_sync(0xffffffffu, rmax1, 2));
        rmax2 = fmaxf(rmax2, __shfl_xor_sync(0xffffffffu, rmax2, 1));
        rmax2 = fmaxf(rmax2, __shfl_xor_sync(0xffffffffu, rmax2, 2));
        float mn1 = fmaxf(m1, rmax1), mn2 = fmaxf(m2, rmax2);
        float al1 = __expf(m1 - mn1),  al2 = __expf(m2 - mn2);
        float rs1 = 0.0f, rs2 = 0.0f;
        #pragma unroll
        for (int nt = 0; nt < 8; nt++) {
            sacc[nt][0] = __expf(sacc[nt][0] - mn1);
            sacc[nt][1] = __expf(sacc[nt][1] - mn1);
            sacc[nt][2] = __expf(sacc[nt][2] - mn2);
            sacc[nt][3] = __expf(sacc[nt][3] - mn2);
            rs1 += sacc[nt][0] + sacc[nt][1];
            rs2 += sacc[nt][2] + sacc[nt][3];
        }
        rs1 += __shfl_xor_sync(0xffffffffu, rs1, 1);
        rs1 += __shfl_xor_sync(0xffffffffu, rs1, 2);
        rs2 += __shfl_xor_sync(0xffffffffu, rs2, 1);
        rs2 += __shfl_xor_sync(0xffffffffu, rs2, 2);
        l1 = l1 * al1 + rs1;  m1 = mn1;
        l2 = l2 * al2 + rs2;  m2 = mn2;

        #pragma unroll
        for (int nt = 0; nt < 16; nt++) {
            oacc[nt][0] *= al1; oacc[nt][1] *= al1;
            oacc[nt][2] *= al2; oacc[nt][3] *= al2;
        }

        // ---- pack P into A-fragments (4 ktiles of 16) ----
        unsigned ap[4][4];
        #pragma unroll
        for (int kt = 0; kt < 4; kt++) {
            ap[kt][0] = packbf2(sacc[2*kt][0],   sacc[2*kt][1]);
            ap[kt][1] = packbf2(sacc[2*kt][2],   sacc[2*kt][3]);
            ap[kt][2] = packbf2(sacc[2*kt+1][0], sacc[2*kt+1][1]);
            ap[kt][3] = packbf2(sacc[2*kt+1][2], sacc[2*kt+1][3]);
        }

        // ---- O += P V ----
        const bf16* Vs = Vbuf[cur];
        #pragma unroll
        for (int kt = 0; kt < 4; kt++) {
            #pragma unroll
            for (int nt = 0; nt < 16; nt++) {
                unsigned vb0, vb1;
                unsigned va = (unsigned)__cvta_generic_to_shared(
                    Vs + (kt * 16 + (lane & 15)) * F_PITCH + nt * 8);
                asm volatile("ldmatrix.sync.aligned.m8n8.x2.trans.shared.b16 {%0,%1}, [%2];"
                             : "=r"(vb0), "=r"(vb1) : "r"(va));
                mma16816(oacc[nt], ap[kt], vb0, vb1);
            }
        }
        __syncthreads();
    }

    // ---- epilogue: out = O / l / sqrt(D) ----
    float s1 = 1.0f / (l1 * 32.0f);
    float s2 = 1.0f / (l2 * 32.0f);
    bf16* dst = g_ao + headoff;
    #pragma unroll
    for (int nt = 0; nt < 16; nt++) {
        int c = nt * 8 + 2 * qt;
        *(unsigned*)(dst + (size_t)grow1 * DHH + c) = packbf2(oacc[nt][0] * s1, oacc[nt][1] * s1);
        *(unsigned*)(dst + (size_t)grow2 * DHH + c) = packbf2(oacc[nt][2] * s2, oacc[nt][3] * s2);
    }
}

// ---------------------------------------------------------------------------
extern "C" void kernel_launch(void* const* d_in, const int* in_sizes, int n_in,
                              void* d_out, int out_size)
{
    const float* q     = (const float*)d_in[0];
    const float* Wq    = (const float*)d_in[1];
    const float* bq    = (const float*)d_in[2];
    const float* Wk    = (const float*)d_in[3];
    const float* bk    = (const float*)d_in[4];
    const float* Wv    = (const float*)d_in[5];
    const float* bv    = (const float*)d_in[6];
    const float* Wo    = (const float*)d_in[7];
    const float* bo    = (const float*)d_in[8];
    const float* gamma = (const float*)d_in[9];
    const float* beta  = (const float*)d_in[10];
    float* out = (float*)d_out;

    cudaFuncSetAttribute(gemm_qkv_kernel, cudaFuncAttributeMaxDynamicSharedMemorySize, GEMM_SMEM);
    cudaFuncSetAttribute(gemm_out_kernel, cudaFuncAttributeMaxDynamicSharedMemorySize, GEMM_SMEM);
    cudaFuncSetAttribute(flash2_kernel,   cudaFuncAttributeMaxDynamicSharedMemorySize, FLASH2_SMEM);

    cvt_w_kernel<<<4096, 1024>>>(Wq, Wk, Wv, Wo);
    ln_kernel<<<MTOT, 256>>>(q, gamma, beta);
    gemm_qkv_kernel<<<dim3(DD / BN, MTOT / BM, 3), 256, GEMM_SMEM>>>(bq, bk, bv);
    flash2_kernel<<<dim3(SS / F_BR, HH, BB), 128, FLASH2_SMEM>>>();
    gemm_out_kernel<<<dim3(DD / BN, MTOT / BM, 1), 256, GEMM_SMEM>>>(bo, q, out);
}

// round 3
// speedup vs baseline: 2.3512x; 1.3463x over previous
#include <cuda_runtime.h>
#include <cuda_bf16.h>

typedef __nv_bfloat16 bf16;

// Problem constants
#define BB   2
#define SS   2048
#define DD   1024
#define HH   8
#define DHH  128
#define MTOT (BB*SS)          // 4096 rows
#define HEADLEN (SS*DHH)      // 262144 elems per (b,h) slice

// GEMM v2 tiling
#define GBM 128
#define GBN 128
#define GBK 64
#define G_STAGE_BYTES 32768            // A(16KB)+B(16KB) per stage
#define G_SMEM (2*G_STAGE_BYTES)       // 65536

// Flash v2 tiling
#define F_BR 64
#define F_BC 64
#define F_PITCH 136
#define F_TILE (F_BC*F_PITCH)
#define FLASH2_SMEM (4*F_TILE*2)       // 69632

// Scratch
__device__ bf16 g_x [MTOT*DD];
__device__ bf16 g_qs[MTOT*DD];
__device__ bf16 g_ks[MTOT*DD];
__device__ bf16 g_vs[MTOT*DD];
__device__ bf16 g_ao[MTOT*DD];
__device__ bf16 g_w [4*DD*DD];

// ---------------------------------------------------------------------------
// PTX helpers
// ---------------------------------------------------------------------------
__device__ __forceinline__ void cpasync16(void* sdst, const void* gsrc)
{
    unsigned sa = (unsigned)__cvta_generic_to_shared(sdst);
    asm volatile("cp.async.cg.shared.global [%0], [%1], 16;\n" :: "r"(sa), "l"(gsrc));
}
#define CP_COMMIT() asm volatile("cp.async.commit_group;\n")
#define CP_WAIT(n)  asm volatile("cp.async.wait_group %0;\n" :: "n"(n))

__device__ __forceinline__ void mma16816(float* c, const unsigned* a, unsigned b0, unsigned b1)
{
    asm volatile(
        "mma.sync.aligned.m16n8k16.row.col.f32.bf16.bf16.f32 "
        "{%0,%1,%2,%3}, {%4,%5,%6,%7}, {%8,%9}, {%0,%1,%2,%3};"
        : "+f"(c[0]), "+f"(c[1]), "+f"(c[2]), "+f"(c[3])
        : "r"(a[0]), "r"(a[1]), "r"(a[2]), "r"(a[3]), "r"(b0), "r"(b1));
}

__device__ __forceinline__ void ldm_x4(unsigned* r, const void* p)
{
    unsigned a = (unsigned)__cvta_generic_to_shared(p);
    asm volatile("ldmatrix.sync.aligned.m8n8.x4.shared.b16 {%0,%1,%2,%3}, [%4];"
                 : "=r"(r[0]), "=r"(r[1]), "=r"(r[2]), "=r"(r[3]) : "r"(a));
}

__device__ __forceinline__ void ldm_x4t(unsigned* r, const void* p)
{
    unsigned a = (unsigned)__cvta_generic_to_shared(p);
    asm volatile("ldmatrix.sync.aligned.m8n8.x4.trans.shared.b16 {%0,%1,%2,%3}, [%4];"
                 : "=r"(r[0]), "=r"(r[1]), "=r"(r[2]), "=r"(r[3]) : "r"(a));
}

__device__ __forceinline__ unsigned packbf2(float x, float y)
{
    __nv_bfloat162 p = __float22bfloat162_rn(make_float2(x, y));
    return *(unsigned*)&p;
}

__device__ __forceinline__ unsigned swz(unsigned off) { return off ^ ((off >> 3) & 0x70); }

// ---------------------------------------------------------------------------
// Weight fp32 -> bf16 convert
// ---------------------------------------------------------------------------
__global__ void cvt_w_kernel(const float* __restrict__ wq, const float* __restrict__ wk,
                             const float* __restrict__ wv, const float* __restrict__ wo)
{
    int idx = blockIdx.x * blockDim.x + threadIdx.x;
    int which = idx >> 20;
    int off   = idx & ((1 << 20) - 1);
    const float* src = (which == 0) ? wq : (which == 1) ? wk : (which == 2) ? wv : wo;
    g_w[idx] = __float2bfloat16(src[off]);
}

// ---------------------------------------------------------------------------
// LayerNorm
// ---------------------------------------------------------------------------
__global__ void ln_kernel(const float* __restrict__ q,
                          const float* __restrict__ gamma,
                          const float* __restrict__ beta)
{
    int row = blockIdx.x;
    int t = threadIdx.x;
    const float4 v = ((const float4*)(q + (size_t)row * DD))[t];
    float s  = v.x + v.y + v.z + v.w;
    float sq = v.x*v.x + v.y*v.y + v.z*v.z + v.w*v.w;
    #pragma unroll
    for (int o = 16; o > 0; o >>= 1) {
        s  += __shfl_xor_sync(0xffffffffu, s,  o);
        sq += __shfl_xor_sync(0xffffffffu, sq, o);
    }
    __shared__ float ss[8], ssq[8];
    if ((t & 31) == 0) { ss[t >> 5] = s; ssq[t >> 5] = sq; }
    __syncthreads();
    if (t == 0) {
        float a = 0.f, bsum = 0.f;
        #pragma unroll
        for (int i = 0; i < 8; i++) { a += ss[i]; bsum += ssq[i]; }
        ss[0] = a; ssq[0] = bsum;
    }
    __syncthreads();
    const float mean = ss[0] * (1.0f / DD);
    const float var  = ssq[0] * (1.0f / DD) - mean * mean;
    const float rstd = rsqrtf(var + 1e-5f);
    const float4 g  = ((const float4*)gamma)[t];
    const float4 be = ((const float4*)beta)[t];
    bf16* out = g_x + (size_t)row * DD + t * 4;
    out[0] = __float2bfloat16((v.x - mean) * rstd * g.x + be.x);
    out[1] = __float2bfloat16((v.y - mean) * rstd * g.y + be.y);
    out[2] = __float2bfloat16((v.z - mean) * rstd * g.z + be.z);
    out[3] = __float2bfloat16((v.w - mean) * rstd * g.w + be.w);
}

// ---------------------------------------------------------------------------
// GEMM v2: C = A @ W^T + bias (+residual). 128x128x64, cp.async double-buffer,
// mma.sync + ldmatrix, direct register epilogue.
// 256 threads = 8 warps (4x2); warp tile 32x64.
// ---------------------------------------------------------------------------
template<bool FINAL>
__device__ __forceinline__ void gemm_body2(const bf16* __restrict__ A,
                                           const bf16* __restrict__ W,
                                           const float* __restrict__ bias,
                                           bf16* __restrict__ outB,
                                           float* __restrict__ outF,
                                           const float* __restrict__ resid)
{
    extern __shared__ char smem[];
    const int tid  = threadIdx.x;
    const int wid  = tid >> 5;
    const int lane = tid & 31;
    const int quad = lane >> 2;
    const int qt   = lane & 3;
    const int wr   = wid >> 1;   // 0..3
    const int wc   = wid & 1;    // 0..1
    const int m0   = blockIdx.y * GBM;
    const int n0   = blockIdx.x * GBN;

    float acc[2][8][4];
    #pragma unroll
    for (int mi = 0; mi < 2; mi++)
        #pragma unroll
        for (int nj = 0; nj < 8; nj++)
            #pragma unroll
            for (int i = 0; i < 4; i++) acc[mi][nj][i] = 0.0f;

    const int lrow = tid >> 3;          // 0..31 (per 4-iter chunk -> 128 rows)
    const int lcb  = (tid & 7) * 16;    // byte col
    const int lce  = (tid & 7) * 8;     // elem col

    // prefetch stage 0
    {
        char* As = smem;
        char* Bs = smem + 16384;
        #pragma unroll
        for (int i = 0; i < 4; i++) {
            int r = lrow + i * 32;
            cpasync16(As + swz(r * 128 + lcb), A + (size_t)(m0 + r) * DD + lce);
            cpasync16(Bs + swz(r * 128 + lcb), W + (size_t)(n0 + r) * DD + lce);
        }
        CP_COMMIT();
    }

    const int KT = DD / GBK;   // 16
    for (int t = 0; t < KT; t++) {
        int cur = t & 1;
        if (t + 1 < KT) {
            char* As = smem + (cur ^ 1) * G_STAGE_BYTES;
            char* Bs = As + 16384;
            int k0 = (t + 1) * GBK;
            #pragma unroll
            for (int i = 0; i < 4; i++) {
                int r = lrow + i * 32;
                cpasync16(As + swz(r * 128 + lcb), A + (size_t)(m0 + r) * DD + k0 + lce);
                cpasync16(Bs + swz(r * 128 + lcb), W + (size_t)(n0 + r) * DD + k0 + lce);
            }
            CP_COMMIT();
            CP_WAIT(1);
        } else {
            CP_WAIT(0);
        }
        __syncthreads();

        const char* As = smem + cur * G_STAGE_BYTES;
        const char* Bs = As + 16384;
        #pragma unroll
        for (int kk = 0; kk < 4; kk++) {
            unsigned af[2][4];
            #pragma unroll
            for (int mi = 0; mi < 2; mi++) {
                int row = wr * 32 + mi * 16 + (lane & 15);
                int cb  = kk * 32 + (lane >> 4) * 16;
                ldm_x4(af[mi], As + swz(row * 128 + cb));
            }
            #pragma unroll
            for (int njp = 0; njp < 4; njp++) {
                unsigned bf[4];
                int row = wc * 64 + njp * 16 + (lane >> 4) * 8 + (lane & 7);
                int cb  = kk * 32 + ((lane >> 3) & 1) * 16;
                ldm_x4(bf, Bs + swz(row * 128 + cb));
                #pragma unroll
                for (int mi = 0; mi < 2; mi++) {
                    mma16816(acc[mi][2 * njp],     af[mi], bf[0], bf[1]);
                    mma16816(acc[mi][2 * njp + 1], af[mi], bf[2], bf[3]);
                }
            }
        }
        __syncthreads();
    }

    // direct epilogue
    #pragma unroll
    for (int mi = 0; mi < 2; mi++) {
        int row1 = m0 + wr * 32 + mi * 16 + quad;
        int row2 = row1 + 8;
        #pragma unroll
        for (int nj = 0; nj < 8; nj++) {
            int col = n0 + wc * 64 + nj * 8 + 2 * qt;
            float2 bv = *(const float2*)(bias + col);
            float v0 = acc[mi][nj][0] + bv.x;
            float v1 = acc[mi][nj][1] + bv.y;
            float v2 = acc[mi][nj][2] + bv.x;
            float v3 = acc[mi][nj][3] + bv.y;
            size_t g1 = (size_t)row1 * DD + col;
            size_t g2 = (size_t)row2 * DD + col;
            if (FINAL) {
                float2 r1 = *(const float2*)(resid + g1);
                float2 r2 = *(const float2*)(resid + g2);
                *(float2*)(outF + g1) = make_float2(v0 + r1.x, v1 + r1.y);
                *(float2*)(outF + g2) = make_float2(v2 + r2.x, v3 + r2.y);
            } else {
                *(unsigned*)(outB + g1) = packbf2(v0, v1);
                *(unsigned*)(outB + g2) = packbf2(v2, v3);
            }
        }
    }
}

__global__ __launch_bounds__(256) void gemm2_qkv(const float* __restrict__ bq,
                                                 const float* __restrict__ bk,
                                                 const float* __restrict__ bv)
{
    int z = blockIdx.z;
    const bf16* W     = g_w + (size_t)z * DD * DD;
    const float* bias = (z == 0) ? bq : (z == 1) ? bk : bv;
    bf16* out         = (z == 0) ? g_qs : (z == 1) ? g_ks : g_vs;
    gemm_body2<false>(g_x, W, bias, out, nullptr, nullptr);
}

__global__ __launch_bounds__(256) void gemm2_out(const float* __restrict__ bo,
                                                 const float* __restrict__ resid,
                                                 float* __restrict__ out)
{
    gemm_body2<true>(g_ao, g_w + (size_t)3 * DD * DD, bo, nullptr, out, resid);
}

// ---------------------------------------------------------------------------
// Flash v2.1: register-resident FA2, ldmatrix.x4 for K and V fragments
// ---------------------------------------------------------------------------
__global__ __launch_bounds__(128) void flash2_kernel()
{
    extern __shared__ bf16 fs[];
    bf16* Kbuf[2] = { fs,              fs + F_TILE };
    bf16* Vbuf[2] = { fs + 2*F_TILE,   fs + 3*F_TILE };

    const int tid  = threadIdx.x;
    const int wid  = tid >> 5;
    const int lane = tid & 31;
    const int quad = lane >> 2;
    const int qt   = lane & 3;
    const int qb   = blockIdx.x;
    const int h    = blockIdx.y;
    const int b    = blockIdx.z;
    const size_t headoff = (size_t)b * SS * DD + (size_t)h * HEADLEN;
    const bf16* Kg = g_ks + headoff;
    const bf16* Vg = g_vs + headoff;

    const int grow1 = qb * F_BR + wid * 16 + quad;
    const int grow2 = grow1 + 8;
    const bf16* Qg = g_qs + headoff;
    unsigned aq[8][4];
    #pragma unroll
    for (int kt = 0; kt < 8; kt++) {
        aq[kt][0] = *(const unsigned*)(Qg + (size_t)grow1 * DHH + kt * 16 + 2 * qt);
        aq[kt][1] = *(const unsigned*)(Qg + (size_t)grow2 * DHH + kt * 16 + 2 * qt);
        aq[kt][2] = *(const unsigned*)(Qg + (size_t)grow1 * DHH + kt * 16 + 2 * qt + 8);
        aq[kt][3] = *(const unsigned*)(Qg + (size_t)grow2 * DHH + kt * 16 + 2 * qt + 8);
    }

    float oacc[16][4];
    #pragma unroll
    for (int nt = 0; nt < 16; nt++)
        #pragma unroll
        for (int i = 0; i < 4; i++) oacc[nt][i] = 0.0f;
    float m1 = -1e30f, m2 = -1e30f, l1 = 0.0f, l2 = 0.0f;

    {
        #pragma unroll
        for (int i = 0; i < 8; i++) {
            int idx = tid + i * 128;
            int r = idx >> 4, c = (idx & 15) * 8;
            cpasync16(Kbuf[0] + r * F_PITCH + c, Kg + (size_t)r * DHH + c);
            cpasync16(Vbuf[0] + r * F_PITCH + c, Vg + (size_t)r * DHH + c);
        }
        CP_COMMIT();
    }

    const int NT = SS / F_BC;   // 32
    for (int t = 0; t < NT; t++) {
        int cur = t & 1;
        if (t + 1 < NT) {
            int nxt = cur ^ 1;
            #pragma unroll
            for (int i = 0; i < 8; i++) {
                int idx = tid + i * 128;
                int r = idx >> 4, c = (idx & 15) * 8;
                cpasync16(Kbuf[nxt] + r * F_PITCH + c, Kg + (size_t)((t + 1) * F_BC + r) * DHH + c);
                cpasync16(Vbuf[nxt] + r * F_PITCH + c, Vg + (size_t)((t + 1) * F_BC + r) * DHH + c);
            }
            CP_COMMIT();
            CP_WAIT(1);
        } else {
            CP_WAIT(0);
        }
        __syncthreads();

        // ---- S = Q K^T via ldmatrix.x4 B-fragments ----
        float sacc[8][4];
        #pragma unroll
        for (int nt = 0; nt < 8; nt++)
            #pragma unroll
            for (int i = 0; i < 4; i++) sacc[nt][i] = 0.0f;

        const bf16* Ks = Kbuf[cur];
        const int krow_off = (lane >> 4) * 8 + (lane & 7);
        const int kcol_off = ((lane >> 3) & 1) * 8;
        #pragma unroll
        for (int kt = 0; kt < 8; kt++) {
            #pragma unroll
            for (int ntp = 0; ntp < 4; ntp++) {
                unsigned bfr[4];
                ldm_x4(bfr, Ks + (ntp * 16 + krow_off) * F_PITCH + kt * 16 + kcol_off);
                mma16816(sacc[2 * ntp],     aq[kt], bfr[0], bfr[1]);
                mma16816(sacc[2 * ntp + 1], aq[kt], bfr[2], bfr[3]);
            }
        }

        // ---- online softmax in registers ----
        float rmax1 = -1e30f, rmax2 = -1e30f;
        #pragma unroll
        for (int nt = 0; nt < 8; nt++) {
            rmax1 = fmaxf(rmax1, fmaxf(sacc[nt][0], sacc[nt][1]));
            rmax2 = fmaxf(rmax2, fmaxf(sacc[nt][2], sacc[nt][3]));
        }
        rmax1 = fmaxf(rmax1, __shfl_xor_sync(0xffffffffu, rmax1, 1));
        rmax1 = fmaxf(rmax1, __shfl_xor_sync(0xffffffffu, rmax1, 2));
        rmax2 = fmaxf(rmax2, __shfl_xor_sync(0xffffffffu, rmax2, 1));
        rmax2 = fmaxf(rmax2, __shfl_xor_sync(0xffffffffu, rmax2, 2));
        float mn1 = fmaxf(m1, rmax1), mn2 = fmaxf(m2, rmax2);
        float al1 = __expf(m1 - mn1),  al2 = __expf(m2 - mn2);
        float rs1 = 0.0f, rs2 = 0.0f;
        #pragma unroll
        for (int nt = 0; nt < 8; nt++) {
            sacc[nt][0] = __expf(sacc[nt][0] - mn1);
            sacc[nt][1] = __expf(sacc[nt][1] - mn1);
            sacc[nt][2] = __expf(sacc[nt][2] - mn2);
            sacc[nt][3] = __expf(sacc[nt][3] - mn2);
            rs1 += sacc[nt][0] + sacc[nt][1];
            rs2 += sacc[nt][2] + sacc[nt][3];
        }
        rs1 += __shfl_xor_sync(0xffffffffu, rs1, 1);
        rs1 += __shfl_xor_sync(0xffffffffu, rs1, 2);
        rs2 += __shfl_xor_sync(0xffffffffu, rs2, 1);
        rs2 += __shfl_xor_sync(0xffffffffu, rs2, 2);
        l1 = l1 * al1 + rs1;  m1 = mn1;
        l2 = l2 * al2 + rs2;  m2 = mn2;

        #pragma unroll
        for (int nt = 0; nt < 16; nt++) {
            oacc[nt][0] *= al1; oacc[nt][1] *= al1;
            oacc[nt][2] *= al2; oacc[nt][3] *= al2;
        }

        unsigned ap[4][4];
        #pragma unroll
        for (int kt = 0; kt < 4; kt++) {
            ap[kt][0] = packbf2(sacc[2*kt][0],   sacc[2*kt][1]);
            ap[kt][1] = packbf2(sacc[2*kt][2],   sacc[2*kt][3]);
            ap[kt][2] = packbf2(sacc[2*kt+1][0], sacc[2*kt+1][1]);
            ap[kt][3] = packbf2(sacc[2*kt+1][2], sacc[2*kt+1][3]);
        }

        // ---- O += P V via ldmatrix.x4.trans ----
        const bf16* Vs = Vbuf[cur];
        #pragma unroll
        for (int kt = 0; kt < 4; kt++) {
            #pragma unroll
            for (int nt = 0; nt < 16; nt += 2) {
                unsigned vb[4];
                ldm_x4t(vb, Vs + (kt * 16 + (lane & 15)) * F_PITCH + (nt + (lane >> 4)) * 8);
                mma16816(oacc[nt],     ap[kt], vb[0], vb[1]);
                mma16816(oacc[nt + 1], ap[kt], vb[2], vb[3]);
            }
        }
        __syncthreads();
    }

    float s1 = 1.0f / (l1 * 32.0f);
    float s2 = 1.0f / (l2 * 32.0f);
    bf16* dst = g_ao + headoff;
    #pragma unroll
    for (int nt = 0; nt < 16; nt++) {
        int c = nt * 8 + 2 * qt;
        *(unsigned*)(dst + (size_t)grow1 * DHH + c) = packbf2(oacc[nt][0] * s1, oacc[nt][1] * s1);
        *(unsigned*)(dst + (size_t)grow2 * DHH + c) = packbf2(oacc[nt][2] * s2, oacc[nt][3] * s2);
    }
}

// ---------------------------------------------------------------------------
extern "C" void kernel_launch(void* const* d_in, const int* in_sizes, int n_in,
                              void* d_out, int out_size)
{
    const float* q     = (const float*)d_in[0];
    const float* Wq    = (const float*)d_in[1];
    const float* bq    = (const float*)d_in[2];
    const float* Wk    = (const float*)d_in[3];
    const float* bk    = (const float*)d_in[4];
    const float* Wv    = (const float*)d_in[5];
    const float* bv    = (const float*)d_in[6];
    const float* Wo    = (const float*)d_in[7];
    const float* bo    = (const float*)d_in[8];
    const float* gamma = (const float*)d_in[9];
    const float* beta  = (const float*)d_in[10];
    float* out = (float*)d_out;

    cudaFuncSetAttribute(gemm2_qkv,    cudaFuncAttributeMaxDynamicSharedMemorySize, G_SMEM);
    cudaFuncSetAttribute(gemm2_out,    cudaFuncAttributeMaxDynamicSharedMemorySize, G_SMEM);
    cudaFuncSetAttribute(flash2_kernel, cudaFuncAttributeMaxDynamicSharedMemorySize, FLASH2_SMEM);

    cvt_w_kernel<<<4096, 1024>>>(Wq, Wk, Wv, Wo);
    ln_kernel<<<MTOT, 256>>>(q, gamma, beta);
    gemm2_qkv<<<dim3(DD / GBN, MTOT / GBM, 3), 256, G_SMEM>>>(bq, bk, bv);
    flash2_kernel<<<dim3(SS / F_BR, HH, BB), 128, FLASH2_SMEM>>>();
    gemm2_out<<<dim3(DD / GBN, MTOT / GBM, 1), 256, G_SMEM>>>(bo, q, out);
}